// round 3
// baseline (speedup 1.0000x reference)
#include <cuda_runtime.h>
#include <cuda_bf16.h>
#include <cstdint>

// Problem dims
#define BATCH  8192
#define UDIM   1024
#define KDIM   2048          // D + U concatenated reduction dim
#define KT     16            // K (tf32 elems) per smem tile
#define NT     (KDIM / KT)   // 128 K-iterations

// CTA tile: 128 (batch) x 128 (4 gates x 32 u-cols)
// 8 warps: warp (wid&1) -> m half (64 rows), (wid>>1) -> gate (32 n-cols)

// ---------------- scratch (device globals; no allocs allowed) ----------------
__device__ __align__(256) float g_A [(size_t)BATCH * KDIM];   // [8192][2048] x|h, tf32-rounded
__device__ __align__(256) float g_Wt[(size_t)4096  * KDIM];   // [4096][2048] [W;U]^T, tf32-rounded

// ---------------- helpers ----------------
__device__ __forceinline__ uint32_t smem_u32(const void* p) {
    uint32_t a;
    asm("{ .reg .u64 t; cvta.to.shared.u64 t, %1; cvt.u32.u64 %0, t; }" : "=r"(a) : "l"(p));
    return a;
}
__device__ __forceinline__ float to_tf32(float x) {
    float r;
    asm("cvt.rna.tf32.f32 %0, %1;" : "=f"(r) : "f"(x));
    return r;
}
__device__ __forceinline__ void cp16(uint32_t dst, const void* src) {
    asm volatile("cp.async.cg.shared.global [%0], [%1], 16;\n" :: "r"(dst), "l"(src));
}
__device__ __forceinline__ void ldsm4(uint32_t* r, uint32_t addr) {
    asm volatile("ldmatrix.sync.aligned.m8n8.x4.shared.b16 {%0,%1,%2,%3}, [%4];\n"
                 : "=r"(r[0]), "=r"(r[1]), "=r"(r[2]), "=r"(r[3]) : "r"(addr));
}
__device__ __forceinline__ void mma_tf32(float* c, const uint32_t* a, uint32_t b0, uint32_t b1) {
    asm volatile(
        "mma.sync.aligned.m16n8k8.row.col.f32.tf32.tf32.f32 "
        "{%0,%1,%2,%3}, {%4,%5,%6,%7}, {%8,%9}, {%0,%1,%2,%3};\n"
        : "+f"(c[0]), "+f"(c[1]), "+f"(c[2]), "+f"(c[3])
        : "r"(a[0]), "r"(a[1]), "r"(a[2]), "r"(a[3]), "r"(b0), "r"(b1));
}

// SMEM: 4 stages; each stage = A tile (128 rows x 64B data, 80B stride)
//       followed by B tile (same). 80B stride -> ldmatrix conflict-free (5r mod 8 distinct).
#define ROWB        80
#define TILE_BYTES  (128 * ROWB)            // 10240
#define STAGE_BYTES (2 * TILE_BYTES)        // 20480
#define NSTAGE      4
#define SMEM_TOTAL  (NSTAGE * STAGE_BYTES)  // 81920

// ---------------- kernel 1: x|h -> tf32 concat ----------------
__global__ void k_conv_act(const float* __restrict__ x, const float* __restrict__ h) {
    int c = blockIdx.x * blockDim.x + threadIdx.x;  // 8-elem chunk id (2M total)
    int m  = c >> 8;
    int kc = (c & 255) << 3;
    const float* src = (kc < 1024) ? (x + (size_t)m * 1024 + kc)
                                   : (h + (size_t)m * 1024 + (kc - 1024));
    float4 a = *(const float4*)src;
    float4 b = *(const float4*)(src + 4);
    a.x = to_tf32(a.x); a.y = to_tf32(a.y); a.z = to_tf32(a.z); a.w = to_tf32(a.w);
    b.x = to_tf32(b.x); b.y = to_tf32(b.y); b.z = to_tf32(b.z); b.w = to_tf32(b.w);
    float* dst = g_A + (size_t)m * KDIM + kc;
    *reinterpret_cast<float4*>(dst)     = a;
    *reinterpret_cast<float4*>(dst + 4) = b;
}

// ---------------- kernel 2: weights -> transposed K-major tf32 ----------------
__global__ void k_conv_w(const float* __restrict__ Wi, const float* __restrict__ Wf,
                         const float* __restrict__ Wc, const float* __restrict__ Wo,
                         const float* __restrict__ Ui, const float* __restrict__ Uf,
                         const float* __restrict__ Uc, const float* __restrict__ Uo) {
    __shared__ float t[32][33];
    int k0 = blockIdx.x * 32;          // 0..2047
    int j0 = blockIdx.y * 32;          // 0..4095
    int g  = j0 >> 10;
    int u0 = j0 & 1023;
    bool isU = (k0 >= 1024);
    int kk = isU ? (k0 - 1024) : k0;
    const float* src;
    if      (g == 0) src = isU ? Ui : Wi;
    else if (g == 1) src = isU ? Uf : Wf;
    else if (g == 2) src = isU ? Uc : Wc;
    else             src = isU ? Uo : Wo;
    int tx = threadIdx.x, ty = threadIdx.y;
    #pragma unroll
    for (int r = 0; r < 32; r += 8)
        t[ty + r][tx] = src[(size_t)(kk + ty + r) * 1024 + u0 + tx];
    __syncthreads();
    #pragma unroll
    for (int r = 0; r < 32; r += 8)
        g_Wt[(size_t)(j0 + ty + r) * KDIM + k0 + tx] = to_tf32(t[tx][ty + r]);
}

// ---------------- kernel 3: pipelined tf32 mma.sync GEMM + fused LSTM ----------------
__global__ __launch_bounds__(256, 2) void k_main(
    const float* __restrict__ c_in,
    const float* __restrict__ Vi, const float* __restrict__ Vf, const float* __restrict__ Vo,
    const float* __restrict__ bi, const float* __restrict__ bff, const float* __restrict__ bcc,
    const float* __restrict__ bo,
    float* __restrict__ out_h, float* __restrict__ out_c)
{
    extern __shared__ __align__(1024) char smem[];
    const uint32_t sb = smem_u32(smem);
    const int tid = threadIdx.x, wid = tid >> 5, lane = tid & 31;
    const int m0 = blockIdx.y * 128;   // batch tile
    const int u0 = blockIdx.x * 32;    // u tile

    // ---- global load tasks: A/B tiles are 128 rows x 16 tf32 (64B).
    // 512 x 16B chunks per tile; 256 threads -> 2 chunks each (per tile).
    const int lrow = tid >> 1;               // 0..127
    const int lc0  = (tid & 1) * 2;          // chunk pair: lc0, lc0+1 (16B chunks)
    const float* ag = g_A + (size_t)(m0 + lrow) * KDIM + lc0 * 4;
    const float* bg = g_Wt + (size_t)((lrow >> 5) * 1024 + u0 + (lrow & 31)) * KDIM + lc0 * 4;
    const uint32_t soff = (uint32_t)(lrow * ROWB + lc0 * 16);

    // prologue: stages 0,1,2
    #pragma unroll
    for (int s = 0; s < NSTAGE - 1; s++) {
        uint32_t base = sb + s * STAGE_BYTES;
        cp16(base + soff,                   ag + s * KT);
        cp16(base + soff + 16,              ag + s * KT + 4);
        cp16(base + TILE_BYTES + soff,      bg + s * KT);
        cp16(base + TILE_BYTES + soff + 16, bg + s * KT + 4);
        asm volatile("cp.async.commit_group;" ::: "memory");
    }

    // ---- ldmatrix per-thread base offsets ----
    const int warp_m = (wid & 1) * 64;
    const int warp_n = (wid >> 1) * 32;   // gate*32 within B tile
    // A x4: r0=a0(rows 0-7,k0-3) r1=a1(rows 8-15,k0-3) r2=a2(rows 0-7,k4-7) r3=a3
    const uint32_t aoff = (uint32_t)((warp_m + (lane & 15)) * ROWB + (lane >> 4) * 16);
    // B x4: r0=b0(n 0-7,k0-3) r1=b1(n 0-7,k4-7) r2=b0(n 8-15,k0-3) r3=b1(n 8-15,k4-7)
    const uint32_t boff = (uint32_t)((warp_n + (lane >> 4) * 8 + (lane & 7)) * ROWB
                                     + ((lane >> 3) & 1) * 16) + TILE_BYTES;

    float acc[4][4][4];
    #pragma unroll
    for (int i = 0; i < 4; i++)
        #pragma unroll
        for (int j = 0; j < 4; j++)
            #pragma unroll
            for (int k = 0; k < 4; k++) acc[i][j][k] = 0.f;

    #pragma unroll 1
    for (int t = 0; t < NT; t++) {
        asm volatile("cp.async.wait_group 2;" ::: "memory");
        __syncthreads();

        // issue loads for stage t+3 (its slot was consumed at iter t-1)
        if (t + NSTAGE - 1 < NT) {
            int s = t + NSTAGE - 1;
            uint32_t base = sb + (s & (NSTAGE - 1)) * STAGE_BYTES;
            cp16(base + soff,                   ag + s * KT);
            cp16(base + soff + 16,              ag + s * KT + 4);
            cp16(base + TILE_BYTES + soff,      bg + s * KT);
            cp16(base + TILE_BYTES + soff + 16, bg + s * KT + 4);
        }
        asm volatile("cp.async.commit_group;" ::: "memory");

        const uint32_t sbase = sb + (t & (NSTAGE - 1)) * STAGE_BYTES;
        #pragma unroll
        for (int ks = 0; ks < 2; ks++) {           // two k8 steps per 16-wide tile
            uint32_t afr[4][4], bfr[2][4];
            #pragma unroll
            for (int mt = 0; mt < 4; mt++)
                ldsm4(afr[mt], sbase + aoff + mt * (16 * ROWB) + ks * 32);
            #pragma unroll
            for (int np = 0; np < 2; np++)         // n-tile pairs {0,1},{2,3}
                ldsm4(bfr[np], sbase + boff + np * (16 * ROWB) + ks * 32);
            #pragma unroll
            for (int mt = 0; mt < 4; mt++)
                #pragma unroll
                for (int nt = 0; nt < 4; nt++)
                    mma_tf32(acc[mt][nt], afr[mt],
                             bfr[nt >> 1][(nt & 1) * 2], bfr[nt >> 1][(nt & 1) * 2 + 1]);
        }
    }

    // -------- fused LSTM epilogue (reuse smem as [4 gates][128 m][33] f32) --------
    __syncthreads();
    float* stage = reinterpret_cast<float*>(smem);
    {
        const int g = wid >> 1;
        const int mb = (wid & 1) * 64 + (lane >> 2);
        const int ub = (lane & 3) * 2;
        #pragma unroll
        for (int mt = 0; mt < 4; mt++) {
            #pragma unroll
            for (int nt = 0; nt < 4; nt++) {
                const int u = nt * 8 + ub;
                float* p0 = &stage[(size_t)(g * 128 + mb + mt * 16) * 33 + u];
                float* p1 = p0 + 8 * 33;
                p0[0] = acc[mt][nt][0]; p0[1] = acc[mt][nt][1];
                p1[0] = acc[mt][nt][2]; p1[1] = acc[mt][nt][3];
            }
        }
    }
    __syncthreads();

    {
        const int uu = lane;
        const int ug = u0 + uu;
        const float vi = Vi[ug], vf = Vf[ug], vo = Vo[ug];
        const float vbi = bi[ug], vbf = bff[ug], vbc = bcc[ug], vbo = bo[ug];
        #pragma unroll 4
        for (int rr = wid; rr < 128; rr += 8) {
            const int m = m0 + rr;
            const float cin = c_in[(size_t)m * 1024 + ug];
            const float zi = stage[(size_t)(0 * 128 + rr) * 33 + uu] + vbi;
            const float zf = stage[(size_t)(1 * 128 + rr) * 33 + uu] + vbf;
            const float zc = stage[(size_t)(2 * 128 + rr) * 33 + uu] + vbc;
            const float zo = stage[(size_t)(3 * 128 + rr) * 33 + uu] + vbo;
            const float it  = 1.f / (1.f + expf(-(zi + vi * cin)));
            const float ft  = 1.f / (1.f + expf(-(zf + vf * cin)));
            const float ctl = tanhf(zc);
            const float ct  = ft * cin + it * ctl;
            const float ot  = 1.f / (1.f + expf(-(zo + vo * ct)));
            const float ht  = ot * tanhf(ct);
            out_h[(size_t)m * 1024 + ug] = ht;
            out_c[(size_t)m * 1024 + ug] = ct;
        }
    }
}

// ---------------- launch ----------------
extern "C" void kernel_launch(void* const* d_in, const int* in_sizes, int n_in,
                              void* d_out, int out_size) {
    const float* x  = (const float*)d_in[0];
    const float* h  = (const float*)d_in[1];
    const float* c  = (const float*)d_in[2];
    const float* Wi = (const float*)d_in[3];
    const float* Wf = (const float*)d_in[4];
    const float* Wc = (const float*)d_in[5];
    const float* Wo = (const float*)d_in[6];
    const float* Ui = (const float*)d_in[7];
    const float* Uf = (const float*)d_in[8];
    const float* Uc = (const float*)d_in[9];
    const float* Uo = (const float*)d_in[10];
    const float* Vi = (const float*)d_in[11];
    const float* Vf = (const float*)d_in[12];
    const float* Vo = (const float*)d_in[13];
    const float* bi = (const float*)d_in[14];
    const float* bf = (const float*)d_in[15];
    const float* bc = (const float*)d_in[16];
    const float* bo = (const float*)d_in[17];

    float* out_h = (float*)d_out;
    float* out_c = out_h + (size_t)BATCH * UDIM;

    static bool attr_done = false;
    if (!attr_done) {
        cudaFuncSetAttribute(k_main, cudaFuncAttributeMaxDynamicSharedMemorySize, SMEM_TOTAL);
        attr_done = true;
    }

    k_conv_act<<<8192, 256>>>(x, h);
    k_conv_w<<<dim3(64, 128), dim3(32, 8)>>>(Wi, Wf, Wc, Wo, Ui, Uf, Uc, Uo);
    k_main<<<dim3(32, 64), 256, SMEM_TOTAL>>>(c, Vi, Vf, Vo, bi, bf, bc, bo, out_h, out_c);
}

// round 4
// speedup vs baseline: 1.9208x; 1.9208x over previous
#include <cuda_runtime.h>
#include <cuda_fp16.h>
#include <cstdint>

// Problem dims
#define BATCH  8192
#define UDIM   1024
#define KDIM   2048          // D + U concatenated reduction dim
#define KT     32            // K (fp16 elems) per smem tile
#define NT     (KDIM / KT)   // 64 K-iterations

// CTA tile: 128 (batch) x 128 (4 gates x 32 u-cols)
// 8 warps: warp (wid&1) -> m half (64 rows), (wid>>1) -> gate (32 n-cols)

// ---------------- scratch (device globals; no allocs allowed) ----------------
__device__ __align__(256) __half g_A [(size_t)BATCH * KDIM];   // [8192][2048] x|h fp16
__device__ __align__(256) __half g_Wt[(size_t)4096  * KDIM];   // [4096][2048] [W;U]^T fp16

// ---------------- helpers ----------------
__device__ __forceinline__ uint32_t smem_u32(const void* p) {
    uint32_t a;
    asm("{ .reg .u64 t; cvta.to.shared.u64 t, %1; cvt.u32.u64 %0, t; }" : "=r"(a) : "l"(p));
    return a;
}
__device__ __forceinline__ void cp16(uint32_t dst, const void* src) {
    asm volatile("cp.async.cg.shared.global [%0], [%1], 16;\n" :: "r"(dst), "l"(src));
}
__device__ __forceinline__ void ldsm4(uint32_t* r, uint32_t addr) {
    asm volatile("ldmatrix.sync.aligned.m8n8.x4.shared.b16 {%0,%1,%2,%3}, [%4];\n"
                 : "=r"(r[0]), "=r"(r[1]), "=r"(r[2]), "=r"(r[3]) : "r"(addr));
}
__device__ __forceinline__ void mma16816(float* c, const uint32_t* a, uint32_t b0, uint32_t b1) {
    asm volatile(
        "mma.sync.aligned.m16n8k16.row.col.f32.f16.f16.f32 "
        "{%0,%1,%2,%3}, {%4,%5,%6,%7}, {%8,%9}, {%0,%1,%2,%3};\n"
        : "+f"(c[0]), "+f"(c[1]), "+f"(c[2]), "+f"(c[3])
        : "r"(a[0]), "r"(a[1]), "r"(a[2]), "r"(a[3]), "r"(b0), "r"(b1));
}

// SMEM pipeline: 4 stages; each: A tile (128 rows x 64B data, 80B stride), then B tile.
// 80B stride -> ldmatrix conflict-free.
#define ROWB        80
#define TILE_BYTES  (128 * ROWB)            // 10240
#define STAGE_BYTES (2 * TILE_BYTES)        // 20480
#define NSTAGE      4
#define SMEM_TOTAL  (NSTAGE * STAGE_BYTES)  // 81920

// ---------------- kernel 1: x|h -> fp16 concat ----------------
__global__ void k_conv_act(const float* __restrict__ x, const float* __restrict__ h) {
    int c = blockIdx.x * blockDim.x + threadIdx.x;  // 8-elem chunk id
    int m  = c >> 8;
    int kc = (c & 255) << 3;
    const float* src = (kc < 1024) ? (x + (size_t)m * 1024 + kc)
                                   : (h + (size_t)m * 1024 + (kc - 1024));
    float4 a = *(const float4*)src;
    float4 b = *(const float4*)(src + 4);
    __half2 p0 = __floats2half2_rn(a.x, a.y);
    __half2 p1 = __floats2half2_rn(a.z, a.w);
    __half2 p2 = __floats2half2_rn(b.x, b.y);
    __half2 p3 = __floats2half2_rn(b.z, b.w);
    uint4 o;
    o.x = *reinterpret_cast<uint32_t*>(&p0);
    o.y = *reinterpret_cast<uint32_t*>(&p1);
    o.z = *reinterpret_cast<uint32_t*>(&p2);
    o.w = *reinterpret_cast<uint32_t*>(&p3);
    *reinterpret_cast<uint4*>(g_A + (size_t)m * KDIM + kc) = o;
}

// ---------------- kernel 2: weights -> transposed K-major fp16 ----------------
__global__ void k_conv_w(const float* __restrict__ Wi, const float* __restrict__ Wf,
                         const float* __restrict__ Wc, const float* __restrict__ Wo,
                         const float* __restrict__ Ui, const float* __restrict__ Uf,
                         const float* __restrict__ Uc, const float* __restrict__ Uo) {
    __shared__ float t[32][33];
    int k0 = blockIdx.x * 32;          // 0..2047
    int j0 = blockIdx.y * 32;          // 0..4095
    int g  = j0 >> 10;
    int u0 = j0 & 1023;
    bool isU = (k0 >= 1024);
    int kk = isU ? (k0 - 1024) : k0;
    const float* src;
    if      (g == 0) src = isU ? Ui : Wi;
    else if (g == 1) src = isU ? Uf : Wf;
    else if (g == 2) src = isU ? Uc : Wc;
    else             src = isU ? Uo : Wo;
    int tx = threadIdx.x, ty = threadIdx.y;
    #pragma unroll
    for (int r = 0; r < 32; r += 8)
        t[ty + r][tx] = src[(size_t)(kk + ty + r) * 1024 + u0 + tx];
    __syncthreads();
    #pragma unroll
    for (int r = 0; r < 32; r += 8)
        g_Wt[(size_t)(j0 + ty + r) * KDIM + k0 + tx] = __float2half_rn(t[tx][ty + r]);
}

// ---------------- kernel 3: pipelined fp16 mma.sync GEMM + fused LSTM ----------------
__global__ __launch_bounds__(256, 2) void k_main(
    const float* __restrict__ c_in,
    const float* __restrict__ Vi, const float* __restrict__ Vf, const float* __restrict__ Vo,
    const float* __restrict__ bi, const float* __restrict__ bff, const float* __restrict__ bcc,
    const float* __restrict__ bo,
    float* __restrict__ out_h, float* __restrict__ out_c)
{
    extern __shared__ __align__(1024) char smem[];
    const uint32_t sb = smem_u32(smem);
    const int tid = threadIdx.x, wid = tid >> 5, lane = tid & 31;
    const int m0 = blockIdx.y * 128;   // batch tile
    const int u0 = blockIdx.x * 32;    // u tile

    // ---- global load tasks: thread -> (row = tid>>2 and +64, chunk = tid&3) ----
    const int lrow = tid >> 2, lch = tid & 3;
    const __half* ag0 = g_A + (size_t)(m0 + lrow) * KDIM + lch * 8;
    const __half* ag1 = ag0 + (size_t)64 * KDIM;
    const int r2 = lrow + 64;
    const __half* bg0 = g_Wt + (size_t)((lrow >> 5) * 1024 + u0 + (lrow & 31)) * KDIM + lch * 8;
    const __half* bg1 = g_Wt + (size_t)((r2   >> 5) * 1024 + u0 + (r2   & 31)) * KDIM + lch * 8;
    const uint32_t soff = (uint32_t)(lrow * ROWB + lch * 16);

    // prologue: stages 0,1,2
    #pragma unroll
    for (int s = 0; s < NSTAGE - 1; s++) {
        uint32_t base = sb + s * STAGE_BYTES;
        cp16(base + soff,                          ag0 + s * KT);
        cp16(base + soff + 64 * ROWB,              ag1 + s * KT);
        cp16(base + TILE_BYTES + soff,             bg0 + s * KT);
        cp16(base + TILE_BYTES + soff + 64 * ROWB, bg1 + s * KT);
        asm volatile("cp.async.commit_group;" ::: "memory");
    }

    // ---- ldmatrix per-thread base offsets ----
    const int warp_m = (wid & 1) * 64;
    const int warp_n = (wid >> 1) * 32;   // gate*32 within B tile
    const uint32_t aoff = (uint32_t)((warp_m + (lane & 15)) * ROWB + (lane >> 4) * 16);
    const uint32_t boff = (uint32_t)((warp_n + (lane & 15)) * ROWB + (lane >> 4) * 16) + TILE_BYTES;

    float acc[4][4][4];
    #pragma unroll
    for (int i = 0; i < 4; i++)
        #pragma unroll
        for (int j = 0; j < 4; j++)
            #pragma unroll
            for (int k = 0; k < 4; k++) acc[i][j][k] = 0.f;

    #pragma unroll 1
    for (int t = 0; t < NT; t++) {
        asm volatile("cp.async.wait_group 2;" ::: "memory");
        __syncthreads();

        // issue loads for stage t+3 (slot consumed at iter t-1, synced above)
        if (t + NSTAGE - 1 < NT) {
            int s = t + NSTAGE - 1;
            uint32_t base = sb + (s & (NSTAGE - 1)) * STAGE_BYTES;
            cp16(base + soff,                          ag0 + s * KT);
            cp16(base + soff + 64 * ROWB,              ag1 + s * KT);
            cp16(base + TILE_BYTES + soff,             bg0 + s * KT);
            cp16(base + TILE_BYTES + soff + 64 * ROWB, bg1 + s * KT);
        }
        asm volatile("cp.async.commit_group;" ::: "memory");

        const uint32_t sbase = sb + (t & (NSTAGE - 1)) * STAGE_BYTES;
        #pragma unroll
        for (int ks = 0; ks < 2; ks++) {
            uint32_t afr[4][4], bfr[2][4];
            #pragma unroll
            for (int mt = 0; mt < 4; mt++)
                ldsm4(afr[mt], sbase + aoff + mt * (16 * ROWB) + ks * 32);
            #pragma unroll
            for (int n2 = 0; n2 < 2; n2++)
                ldsm4(bfr[n2], sbase + boff + n2 * (16 * ROWB) + ks * 32);
            #pragma unroll
            for (int mt = 0; mt < 4; mt++)
                #pragma unroll
                for (int nt = 0; nt < 4; nt++)
                    mma16816(acc[mt][nt], afr[mt], bfr[nt >> 1][nt & 1], bfr[nt >> 1][(nt & 1) + 2]);
        }
    }

    // -------- fused LSTM epilogue (reuse smem as [4 gates][128 m][33] f32) --------
    __syncthreads();
    float* stage = reinterpret_cast<float*>(smem);
    {
        const int g = wid >> 1;
        const int mb = (wid & 1) * 64 + (lane >> 2);
        const int ub = (lane & 3) * 2;
        #pragma unroll
        for (int mt = 0; mt < 4; mt++) {
            #pragma unroll
            for (int nt = 0; nt < 4; nt++) {
                const int u = nt * 8 + ub;
                float* p0 = &stage[(size_t)(g * 128 + mb + mt * 16) * 33 + u];
                float* p1 = p0 + 8 * 33;
                p0[0] = acc[mt][nt][0]; p0[1] = acc[mt][nt][1];
                p1[0] = acc[mt][nt][2]; p1[1] = acc[mt][nt][3];
            }
        }
    }
    __syncthreads();

    {
        const int uu = lane;
        const int ug = u0 + uu;
        const float vi = Vi[ug], vf = Vf[ug], vo = Vo[ug];
        const float vbi = bi[ug], vbf = bff[ug], vbc = bcc[ug], vbo = bo[ug];
        #pragma unroll 4
        for (int rr = wid; rr < 128; rr += 8) {
            const int m = m0 + rr;
            const float cin = c_in[(size_t)m * 1024 + ug];
            const float zi = stage[(size_t)(0 * 128 + rr) * 33 + uu] + vbi;
            const float zf = stage[(size_t)(1 * 128 + rr) * 33 + uu] + vbf;
            const float zc = stage[(size_t)(2 * 128 + rr) * 33 + uu] + vbc;
            const float zo = stage[(size_t)(3 * 128 + rr) * 33 + uu] + vbo;
            const float it  = 1.f / (1.f + expf(-(zi + vi * cin)));
            const float ft  = 1.f / (1.f + expf(-(zf + vf * cin)));
            const float ctl = tanhf(zc);
            const float ct  = ft * cin + it * ctl;
            const float ot  = 1.f / (1.f + expf(-(zo + vo * ct)));
            const float ht  = ot * tanhf(ct);
            out_h[(size_t)m * 1024 + ug] = ht;
            out_c[(size_t)m * 1024 + ug] = ct;
        }
    }
}

// ---------------- launch ----------------
extern "C" void kernel_launch(void* const* d_in, const int* in_sizes, int n_in,
                              void* d_out, int out_size) {
    const float* x  = (const float*)d_in[0];
    const float* h  = (const float*)d_in[1];
    const float* c  = (const float*)d_in[2];
    const float* Wi = (const float*)d_in[3];
    const float* Wf = (const float*)d_in[4];
    const float* Wc = (const float*)d_in[5];
    const float* Wo = (const float*)d_in[6];
    const float* Ui = (const float*)d_in[7];
    const float* Uf = (const float*)d_in[8];
    const float* Uc = (const float*)d_in[9];
    const float* Uo = (const float*)d_in[10];
    const float* Vi = (const float*)d_in[11];
    const float* Vf = (const float*)d_in[12];
    const float* Vo = (const float*)d_in[13];
    const float* bi = (const float*)d_in[14];
    const float* bf = (const float*)d_in[15];
    const float* bc = (const float*)d_in[16];
    const float* bo = (const float*)d_in[17];

    float* out_h = (float*)d_out;
    float* out_c = out_h + (size_t)BATCH * UDIM;

    static bool attr_done = false;
    if (!attr_done) {
        cudaFuncSetAttribute(k_main, cudaFuncAttributeMaxDynamicSharedMemorySize, SMEM_TOTAL);
        attr_done = true;
    }

    k_conv_act<<<8192, 256>>>(x, h);
    k_conv_w<<<dim3(64, 128), dim3(32, 8)>>>(Wi, Wf, Wc, Wo, Ui, Uf, Uc, Uo);
    k_main<<<dim3(32, 64), 256, SMEM_TOTAL>>>(c, Vi, Vf, Vo, bi, bf, bc, bo, out_h, out_c);
}